// round 13
// baseline (speedup 1.0000x reference)
#include <cuda_runtime.h>
#include <cuda_fp16.h>
#include <cstdint>

#define B_    64
#define J_    1024
#define M_    256
#define NC_   32
#define DC_   32
#define EPS_  1e-7f
#define XSEG_ 8      // xsum partial segments (128 j each)
#define CSEG_ 16     // cx partial segments (64 j each)

// Scratch
__device__ float  g_xsump[XSEG_ * B_ * M_];
__device__ float  g_cxp  [CSEG_ * B_ * NC_ * M_];
__device__ float  g_cx   [B_ * NC_ * M_];
__device__ __half g_wvh  [B_ * NC_ * M_];
__device__ __half g_wvl  [B_ * NC_ * M_];
__device__ __half g_xh   [B_ * J_ * M_];     // x hi plane, row layout [b][j][m]
__device__ __half g_xl   [B_ * J_ * M_];     // x lo plane (x4096)

// ---------- helpers ----------
__device__ __forceinline__ void splitf(float f, __half& h, __half& l) {
    h = __float2half_rn(f);
    l = __float2half_rn((f - __half2float(h)) * 4096.0f);
}

__device__ __forceinline__ void mma16816(float& c0, float& c1, float& c2, float& c3,
                                         uint32_t a0, uint32_t a1, uint32_t a2, uint32_t a3,
                                         uint32_t b0, uint32_t b1) {
    asm volatile(
        "mma.sync.aligned.m16n8k16.row.col.f32.f16.f16.f32 "
        "{%0,%1,%2,%3}, {%4,%5,%6,%7}, {%8,%9}, {%0,%1,%2,%3};"
        : "+f"(c0), "+f"(c1), "+f"(c2), "+f"(c3)
        : "r"(a0), "r"(a1), "r"(a2), "r"(a3), "r"(b0), "r"(b1));
}

__device__ __forceinline__ void ldmx4(uint32_t& r0, uint32_t& r1, uint32_t& r2, uint32_t& r3,
                                      uint32_t addr) {
    asm volatile(
        "ldmatrix.sync.aligned.m8n8.x4.shared.b16 {%0,%1,%2,%3}, [%4];"
        : "=r"(r0), "=r"(r1), "=r"(r2), "=r"(r3) : "r"(addr));
}
__device__ __forceinline__ void ldmx4t(uint32_t& r0, uint32_t& r1, uint32_t& r2, uint32_t& r3,
                                       uint32_t addr) {
    asm volatile(
        "ldmatrix.sync.aligned.m8n8.x4.trans.shared.b16 {%0,%1,%2,%3}, [%4];"
        : "=r"(r0), "=r"(r1), "=r"(r2), "=r"(r3) : "r"(addr));
}
__device__ __forceinline__ void cpa16(uint32_t smem, const void* g) {
    asm volatile("cp.async.cg.shared.global [%0], [%1], 16;" :: "r"(smem), "l"(g));
}
#define CP_COMMIT asm volatile("cp.async.commit_group;")
#define CP_WAIT0  asm volatile("cp.async.wait_group 0;")

// ---------- prep: x -> hi/lo row planes [b][j][m] + xsum partials ----------
__global__ void __launch_bounds__(256) k_prep(const float* __restrict__ x) {
    __shared__ float4 sred[4][64];
    int b = blockIdx.x, seg = blockIdx.y;
    int t = threadIdx.x;
    int jj = t >> 6, mq = t & 63;
    float4 s = {0.f, 0.f, 0.f, 0.f};
    for (int it = 0; it < 32; ++it) {
        int j = seg * 128 + jj + 4 * it;
        size_t off = ((size_t)b * J_ + j) * M_ + mq * 4;
        float4 v = *(const float4*)(x + off);
        __half h0, l0, h1, l1, h2, l2, h3, l3;
        splitf(v.x, h0, l0); splitf(v.y, h1, l1);
        splitf(v.z, h2, l2); splitf(v.w, h3, l3);
        uint2 uh, ul;
        ((__half2*)&uh)[0] = __halves2half2(h0, h1);
        ((__half2*)&uh)[1] = __halves2half2(h2, h3);
        ((__half2*)&ul)[0] = __halves2half2(l0, l1);
        ((__half2*)&ul)[1] = __halves2half2(l2, l3);
        *(uint2*)(g_xh + off) = uh;
        *(uint2*)(g_xl + off) = ul;
        s.x += v.x; s.y += v.y; s.z += v.z; s.w += v.w;
    }
    sred[jj][mq] = s;
    __syncthreads();
    if (t < 64) {
        float4 a = sred[0][t], c1 = sred[1][t], c2 = sred[2][t], c3 = sred[3][t];
        a.x += c1.x + c2.x + c3.x; a.y += c1.y + c2.y + c3.y;
        a.z += c1.z + c2.z + c3.z; a.w += c1.w + c2.w + c3.w;
        *(float4*)(g_xsump + ((size_t)seg * B_ + b) * M_ + t * 4) = a;
    }
}

// ---------- red: g_cxp[16 seg] -> g_cx, fully parallel ----------
__global__ void __launch_bounds__(256) k_red() {
    int bi = blockIdx.x;                 // 0..2047 = (b, i)
    int t = threadIdx.x;
    size_t o = (size_t)bi * M_ + t;
    float s = 0.f;
#pragma unroll
    for (int sg = 0; sg < CSEG_; ++sg)
        s += g_cxp[(size_t)sg * B_ * NC_ * M_ + o];
    g_cx[o] = s;
}

// ---------- caps: grid (32 i, 64 b), one (b,i) per block ----------
// out = squash(row @ W_i); Wv = W_i @ out (hi/lo halves)
template <int MODE>
__global__ void __launch_bounds__(256) k_caps(const float* __restrict__ W, float* __restrict__ out) {
    __shared__ float Wsh[M_ * 33];
    __shared__ float rowsh[M_];
    __shared__ float psh[8 * 32];
    __shared__ float osh[NC_];
    int t = threadIdx.x;
    int i = blockIdx.x, b = blockIdx.y;

#pragma unroll
    for (int c = 0; c < 32; ++c) {
        int lin = t + 256 * c;
        int m = lin >> 5, k = lin & 31;
        Wsh[m * 33 + k] = W[m * (NC_ * DC_) + i * DC_ + k];
    }

    float r;
    if (MODE == 0) {
        r = 0.f;
#pragma unroll
        for (int s = 0; s < XSEG_; ++s) r += g_xsump[((size_t)s * B_ + b) * M_ + t];
    } else {
        r = g_cx[((size_t)b * NC_ + i) * M_ + t];
    }
    rowsh[t] = r;
    __syncthreads();

    {
        int k = t & 31, g = t >> 5;
        float p = 0.f;
#pragma unroll
        for (int mm = 0; mm < 32; ++mm)
            p += rowsh[g * 32 + mm] * Wsh[(g * 32 + mm) * 33 + k];
        psh[g * 32 + k] = p;
    }
    __syncthreads();

    if (t < 32) {
        float s = 0.f;
#pragma unroll
        for (int g = 0; g < 8; ++g) s += psh[g * 32 + t];
        float v = (MODE == 0) ? s * (1.0f / 32.0f) : s;
        float sq = v * v;
#pragma unroll
        for (int off = 16; off; off >>= 1) sq += __shfl_xor_sync(0xffffffffu, sq, off);
        float o = v / sqrtf(sq + EPS_);
        osh[t] = o;
        if (MODE == 2) out[((size_t)b * NC_ + i) * DC_ + t] = o;
    }
    __syncthreads();

    if (MODE != 2) {
        float wv = 0.f;
#pragma unroll
        for (int k = 0; k < 32; ++k) wv += Wsh[t * 33 + k] * osh[k];
        __half h, l;
        splitf(wv, h, l);
        g_wvh[((size_t)b * NC_ + i) * M_ + t] = h;
        g_wvl[((size_t)b * NC_ + i) * M_ + t] = l;
    }
}

// ---------- fused route: logits + softmax + cx, x staged once ----------
// grid (64 b, 16 seg64), block 256 = 8 warps. Block: 64 j x (32 i logits; 32i x 256m cx).
// smem halves: XH @0 (64*264), XL @16896, CH @33792 (64*40), CL @36352; b1 f32 @38912.
#define RT_XH 0
#define RT_XL 16896
#define RT_CH 33792
#define RT_CL 36352
#define RT_B1 38912
#define RT_SMEM ((38912 + 4224) * 2)     // 86272 B

__global__ void __launch_bounds__(256, 2) k_route() {
    extern __shared__ __half dsm[];
    uint32_t sb = (uint32_t)__cvta_generic_to_shared(dsm);
    int t = threadIdx.x, lane = t & 31, w = t >> 5;
    int g = lane >> 2, tig = lane & 3;
    int b = blockIdx.x, seg = blockIdx.y, j0 = seg * 64;

    // ---- stage X hi/lo [64 j][256 m], pitch 264 ----
#pragma unroll
    for (int c = 0; c < 8; ++c) {
        int lin = t + 256 * c;              // 2048 uint4 per plane
        int j = lin >> 5, mq = lin & 31;
        size_t so = ((size_t)b * J_ + j0 + j) * M_ + mq * 8;
        cpa16(sb + 2u * (RT_XH + j * 264 + mq * 8), g_xh + so);
        cpa16(sb + 2u * (RT_XL + j * 264 + mq * 8), g_xl + so);
    }
    CP_COMMIT; CP_WAIT0;
    __syncthreads();

    // ---- phase 1: logits. warp: jt = w&3 (16 j), ih = w>>2 (16 i = 2 n-tiles) ----
    {
        int jt = w & 3, ih = w >> 2;
        uint32_t aA = sb + 2u * (RT_XH + (jt * 16 + (lane & 15)) * 264) + (lane >> 4) * 16;
        const uint32_t* wvh0 = (const uint32_t*)(g_wvh + ((size_t)b * NC_ + ih * 16 + g) * M_) + tig;
        const uint32_t* wvl0 = (const uint32_t*)(g_wvl + ((size_t)b * NC_ + ih * 16 + g) * M_) + tig;

        float hh[2][4] = {}, lo[2][4] = {};
#pragma unroll
        for (int ks = 0; ks < 16; ++ks) {
            uint32_t ah0, ah1, ah2, ah3, al0, al1, al2, al3;
            ldmx4(ah0, ah1, ah2, ah3, aA + ks * 32);
            ldmx4(al0, al1, al2, al3, aA + 2u * RT_XL + ks * 32);
            uint32_t bh0 = wvh0[ks * 8],        bh1 = wvh0[ks * 8 + 4];
            uint32_t bh2 = wvh0[1024 + ks * 8], bh3 = wvh0[1024 + ks * 8 + 4];
            uint32_t bl0 = wvl0[ks * 8],        bl1 = wvl0[ks * 8 + 4];
            uint32_t bl2 = wvl0[1024 + ks * 8], bl3 = wvl0[1024 + ks * 8 + 4];
            mma16816(hh[0][0], hh[0][1], hh[0][2], hh[0][3], ah0, ah1, ah2, ah3, bh0, bh1);
            mma16816(lo[0][0], lo[0][1], lo[0][2], lo[0][3], al0, al1, al2, al3, bh0, bh1);
            mma16816(lo[0][0], lo[0][1], lo[0][2], lo[0][3], ah0, ah1, ah2, ah3, bl0, bl1);
            mma16816(hh[1][0], hh[1][1], hh[1][2], hh[1][3], ah0, ah1, ah2, ah3, bh2, bh3);
            mma16816(lo[1][0], lo[1][1], lo[1][2], lo[1][3], al0, al1, al2, al3, bh2, bh3);
            mma16816(lo[1][0], lo[1][1], lo[1][2], lo[1][3], ah0, ah1, ah2, ah3, bl2, bl3);
        }

        float* b1 = (float*)(dsm + RT_B1);
#pragma unroll
        for (int nt = 0; nt < 2; ++nt) {
            int row = jt * 16 + g, col = ih * 16 + nt * 8 + 2 * tig;
            b1[row * 33 + col]           = hh[nt][0] + lo[nt][0] * (1.0f / 4096.0f);
            b1[row * 33 + col + 1]       = hh[nt][1] + lo[nt][1] * (1.0f / 4096.0f);
            b1[(row + 8) * 33 + col]     = hh[nt][2] + lo[nt][2] * (1.0f / 4096.0f);
            b1[(row + 8) * 33 + col + 1] = hh[nt][3] + lo[nt][3] * (1.0f / 4096.0f);
        }
    }
    __syncthreads();

    // ---- phase 2: softmax over i per j; c hi/lo -> smem tiles [j][i] pitch 40 ----
    if (t < 64) {
        float* row = (float*)(dsm + RT_B1) + t * 33;
        float mx = row[0];
#pragma unroll
        for (int i = 1; i < 32; ++i) mx = fmaxf(mx, row[i]);
        float s = 0.f;
        float e[32];
#pragma unroll
        for (int i = 0; i < 32; ++i) { e[i] = __expf(row[i] - mx); s += e[i]; }
        float inv = 1.0f / s;
#pragma unroll
        for (int i2 = 0; i2 < 16; ++i2) {
            __half h0, l0, h1, l1;
            splitf(e[2 * i2] * inv, h0, l0);
            splitf(e[2 * i2 + 1] * inv, h1, l1);
            *(__half2*)(dsm + RT_CH + t * 40 + 2 * i2) = __halves2half2(h0, h1);
            *(__half2*)(dsm + RT_CL + t * 40 + 2 * i2) = __halves2half2(l0, l1);
        }
    }
    __syncthreads();

    // ---- phase 3: cx[i][m] = sum_j c[j][i] x[j][m] over this block's 64 j ----
    {
        int mb = w * 32;
        uint32_t cA = sb + 2u * (RT_CH + ((((lane >> 4) & 1) * 8) + (lane & 7)) * 40
                                 + ((lane >> 3) & 1) * 8);
        uint32_t xB = sb + 2u * (RT_XH + ((((lane >> 3) & 1) * 8) + (lane & 7)) * 264
                                 + mb + ((lane >> 4) & 1) * 8);

        float chh[2][4][4] = {}, clo[2][4][4] = {};
#pragma unroll
        for (int ks = 0; ks < 4; ++ks) {          // K = 64 j
            uint32_t a0h0, a0h1, a0h2, a0h3, a1h0, a1h1, a1h2, a1h3;
            uint32_t a0l0, a0l1, a0l2, a0l3, a1l0, a1l1, a1l2, a1l3;
            ldmx4t(a0h0, a0h1, a0h2, a0h3, cA + ks * 1280);
            ldmx4t(a1h0, a1h1, a1h2, a1h3, cA + 32 + ks * 1280);
            ldmx4t(a0l0, a0l1, a0l2, a0l3, cA + 5120 + ks * 1280);
            ldmx4t(a1l0, a1l1, a1l2, a1l3, cA + 5120 + 32 + ks * 1280);

            uint32_t b0h0, b0h1, b0h2, b0h3, b1h0, b1h1, b1h2, b1h3;
            uint32_t b0l0, b0l1, b0l2, b0l3, b1l0, b1l1, b1l2, b1l3;
            ldmx4t(b0h0, b0h1, b0h2, b0h3, xB + ks * 8448);
            ldmx4t(b1h0, b1h1, b1h2, b1h3, xB + 32 + ks * 8448);
            ldmx4t(b0l0, b0l1, b0l2, b0l3, xB + 2u * RT_XL + ks * 8448);
            ldmx4t(b1l0, b1l1, b1l2, b1l3, xB + 2u * RT_XL + 32 + ks * 8448);

#define CX_MMA(it, AH0,AH1,AH2,AH3, AL0,AL1,AL2,AL3) \
            mma16816(chh[it][0][0], chh[it][0][1], chh[it][0][2], chh[it][0][3], AH0,AH1,AH2,AH3, b0h0, b0h1); \
            mma16816(clo[it][0][0], clo[it][0][1], clo[it][0][2], clo[it][0][3], AL0,AL1,AL2,AL3, b0h0, b0h1); \
            mma16816(clo[it][0][0], clo[it][0][1], clo[it][0][2], clo[it][0][3], AH0,AH1,AH2,AH3, b0l0, b0l1); \
            mma16816(chh[it][1][0], chh[it][1][1], chh[it][1][2], chh[it][1][3], AH0,AH1,AH2,AH3, b0h2, b0h3); \
            mma16816(clo[it][1][0], clo[it][1][1], clo[it][1][2], clo[it][1][3], AL0,AL1,AL2,AL3, b0h2, b0h3); \
            mma16816(clo[it][1][0], clo[it][1][1], clo[it][1][2], clo[it][1][3], AH0,AH1,AH2,AH3, b0l2, b0l3); \
            mma16816(chh[it][2][0], chh[it][2][1], chh[it][2][2], chh[it][2][3], AH0,AH1,AH2,AH3, b1h0, b1h1); \
            mma16816(clo[it][2][0], clo[it][2][1], clo[it][2][2], clo[it][2][3], AL0,AL1,AL2,AL3, b1h0, b1h1); \
            mma16816(clo[it][2][0], clo[it][2][1], clo[it][2][2], clo[it][2][3], AH0,AH1,AH2,AH3, b1l0, b1l1); \
            mma16816(chh[it][3][0], chh[it][3][1], chh[it][3][2], chh[it][3][3], AH0,AH1,AH2,AH3, b1h2, b1h3); \
            mma16816(clo[it][3][0], clo[it][3][1], clo[it][3][2], clo[it][3][3], AL0,AL1,AL2,AL3, b1h2, b1h3); \
            mma16816(clo[it][3][0], clo[it][3][1], clo[it][3][2], clo[it][3][3], AH0,AH1,AH2,AH3, b1l2, b1l3);

            CX_MMA(0, a0h0, a0h1, a0h2, a0h3, a0l0, a0l1, a0l2, a0l3)
            CX_MMA(1, a1h0, a1h1, a1h2, a1h3, a1l0, a1l1, a1l2, a1l3)
#undef CX_MMA
        }

#pragma unroll
        for (int it = 0; it < 2; ++it)
#pragma unroll
            for (int nt = 0; nt < 4; ++nt) {
                int i = it * 16 + g;
                int m = mb + nt * 8 + 2 * tig;
                size_t base = (((size_t)seg * B_ + b) * NC_ + i) * M_ + m;
                float2 v0, v1;
                v0.x = chh[it][nt][0] + clo[it][nt][0] * (1.0f / 4096.0f);
                v0.y = chh[it][nt][1] + clo[it][nt][1] * (1.0f / 4096.0f);
                v1.x = chh[it][nt][2] + clo[it][nt][2] * (1.0f / 4096.0f);
                v1.y = chh[it][nt][3] + clo[it][nt][3] * (1.0f / 4096.0f);
                *(float2*)(g_cxp + base)          = v0;
                *(float2*)(g_cxp + base + 8 * M_) = v1;
            }
    }
}

extern "C" void kernel_launch(void* const* d_in, const int* in_sizes, int n_in,
                              void* d_out, int out_size) {
    const float* x = (const float*)d_in[0];
    const float* W = (const float*)d_in[1];
    if (n_in >= 2 && in_sizes[0] < in_sizes[1]) {
        const float* tmp = x; x = W; W = tmp;
    }
    float* out = (float*)d_out;

    cudaFuncSetAttribute(k_route, cudaFuncAttributeMaxDynamicSharedMemorySize, RT_SMEM);

    k_prep<<<dim3(B_, XSEG_), 256>>>(x);
    k_caps<0><<<dim3(NC_, B_), 256>>>(W, out);

    k_route<<<dim3(B_, CSEG_), 256, RT_SMEM>>>();
    k_red<<<B_ * NC_, 256>>>();
    k_caps<1><<<dim3(NC_, B_), 256>>>(W, out);

    k_route<<<dim3(B_, CSEG_), 256, RT_SMEM>>>();
    k_red<<<B_ * NC_, 256>>>();
    k_caps<2><<<dim3(NC_, B_), 256>>>(W, out);
}

// round 14
// speedup vs baseline: 1.0890x; 1.0890x over previous
#include <cuda_runtime.h>
#include <cuda_fp16.h>
#include <cstdint>

#define B_    64
#define J_    1024
#define M_    256
#define NC_   32
#define DC_   32
#define EPS_  1e-7f
#define XSEG_ 8      // xsum partial segments (128 j each)
#define CSEG_ 16     // cx partial segments (64 j each)

// Scratch
__device__ float  g_xsump[XSEG_ * B_ * M_];
__device__ float  g_cxp  [CSEG_ * B_ * NC_ * M_];
__device__ __half g_wvh  [B_ * NC_ * M_];
__device__ __half g_wvl  [B_ * NC_ * M_];
__device__ __half g_xh   [B_ * J_ * M_];     // x hi plane, row layout [b][j][m]
__device__ __half g_xl   [B_ * J_ * M_];     // x lo plane (x4096)

// ---------- helpers ----------
__device__ __forceinline__ void splitf(float f, __half& h, __half& l) {
    h = __float2half_rn(f);
    l = __float2half_rn((f - __half2float(h)) * 4096.0f);
}

__device__ __forceinline__ void mma16816(float& c0, float& c1, float& c2, float& c3,
                                         uint32_t a0, uint32_t a1, uint32_t a2, uint32_t a3,
                                         uint32_t b0, uint32_t b1) {
    asm volatile(
        "mma.sync.aligned.m16n8k16.row.col.f32.f16.f16.f32 "
        "{%0,%1,%2,%3}, {%4,%5,%6,%7}, {%8,%9}, {%0,%1,%2,%3};"
        : "+f"(c0), "+f"(c1), "+f"(c2), "+f"(c3)
        : "r"(a0), "r"(a1), "r"(a2), "r"(a3), "r"(b0), "r"(b1));
}

__device__ __forceinline__ void ldmx4(uint32_t& r0, uint32_t& r1, uint32_t& r2, uint32_t& r3,
                                      uint32_t addr) {
    asm volatile(
        "ldmatrix.sync.aligned.m8n8.x4.shared.b16 {%0,%1,%2,%3}, [%4];"
        : "=r"(r0), "=r"(r1), "=r"(r2), "=r"(r3) : "r"(addr));
}
__device__ __forceinline__ void ldmx4t(uint32_t& r0, uint32_t& r1, uint32_t& r2, uint32_t& r3,
                                       uint32_t addr) {
    asm volatile(
        "ldmatrix.sync.aligned.m8n8.x4.trans.shared.b16 {%0,%1,%2,%3}, [%4];"
        : "=r"(r0), "=r"(r1), "=r"(r2), "=r"(r3) : "r"(addr));
}
__device__ __forceinline__ void cpa16(uint32_t smem, const void* g) {
    asm volatile("cp.async.cg.shared.global [%0], [%1], 16;" :: "r"(smem), "l"(g));
}
#define CP_COMMIT asm volatile("cp.async.commit_group;")
#define CP_WAIT0  asm volatile("cp.async.wait_group 0;")

// ---------- prep: x -> hi/lo row planes [b][j][m] + xsum partials ----------
__global__ void __launch_bounds__(256) k_prep(const float* __restrict__ x) {
    __shared__ float4 sred[4][64];
    int b = blockIdx.x, seg = blockIdx.y;
    int t = threadIdx.x;
    int jj = t >> 6, mq = t & 63;
    float4 s = {0.f, 0.f, 0.f, 0.f};
    for (int it = 0; it < 32; ++it) {
        int j = seg * 128 + jj + 4 * it;
        size_t off = ((size_t)b * J_ + j) * M_ + mq * 4;
        float4 v = *(const float4*)(x + off);
        __half h0, l0, h1, l1, h2, l2, h3, l3;
        splitf(v.x, h0, l0); splitf(v.y, h1, l1);
        splitf(v.z, h2, l2); splitf(v.w, h3, l3);
        uint2 uh, ul;
        ((__half2*)&uh)[0] = __halves2half2(h0, h1);
        ((__half2*)&uh)[1] = __halves2half2(h2, h3);
        ((__half2*)&ul)[0] = __halves2half2(l0, l1);
        ((__half2*)&ul)[1] = __halves2half2(l2, l3);
        *(uint2*)(g_xh + off) = uh;
        *(uint2*)(g_xl + off) = ul;
        s.x += v.x; s.y += v.y; s.z += v.z; s.w += v.w;
    }
    sred[jj][mq] = s;
    __syncthreads();
    if (t < 64) {
        float4 a = sred[0][t], c1 = sred[1][t], c2 = sred[2][t], c3 = sred[3][t];
        a.x += c1.x + c2.x + c3.x; a.y += c1.y + c2.y + c3.y;
        a.z += c1.z + c2.z + c3.z; a.w += c1.w + c2.w + c3.w;
        *(float4*)(g_xsump + ((size_t)seg * B_ + b) * M_ + t * 4) = a;
    }
}

// ---------- caps: grid (32 i, 16 bg), 4 batches, gathers hoisted upfront ----------
// out = squash(row @ W_i); Wv = W_i @ out (hi/lo halves)
template <int MODE>
__global__ void __launch_bounds__(256) k_caps(const float* __restrict__ W, float* __restrict__ out) {
    __shared__ float Wsh[M_ * 33];
    __shared__ float rows[4][M_ + 4];
    __shared__ float psh[8 * 32];
    __shared__ float osh[NC_];
    int t = threadIdx.x;
    int i = blockIdx.x, bg = blockIdx.y;

    // stage W slice once (16 MB total across grid)
#pragma unroll
    for (int c = 0; c < 32; ++c) {
        int lin = t + 256 * c;
        int m = lin >> 5, k = lin & 31;
        Wsh[m * 33 + k] = W[m * (NC_ * DC_) + i * DC_ + k];
    }

    // hoisted gathers: all 4 batches' segment sums issued together (deep MLP)
#pragma unroll
    for (int bb = 0; bb < 4; ++bb) {
        int b = bg * 4 + bb;
        float r = 0.f;
        if (MODE == 0) {
#pragma unroll
            for (int s = 0; s < XSEG_; ++s) r += g_xsump[((size_t)s * B_ + b) * M_ + t];
        } else {
#pragma unroll
            for (int s = 0; s < CSEG_; ++s)
                r += g_cxp[(((size_t)s * B_ + b) * NC_ + i) * M_ + t];
        }
        rows[bb][t] = r;
    }
    __syncthreads();

    for (int bb = 0; bb < 4; ++bb) {
        int b = bg * 4 + bb;
        {
            int k = t & 31, g = t >> 5;
            float p = 0.f;
#pragma unroll
            for (int mm = 0; mm < 32; ++mm)
                p += rows[bb][g * 32 + mm] * Wsh[(g * 32 + mm) * 33 + k];
            psh[g * 32 + k] = p;
        }
        __syncthreads();

        if (t < 32) {
            float s = 0.f;
#pragma unroll
            for (int g = 0; g < 8; ++g) s += psh[g * 32 + t];
            float v = (MODE == 0) ? s * (1.0f / 32.0f) : s;
            float sq = v * v;
#pragma unroll
            for (int off = 16; off; off >>= 1) sq += __shfl_xor_sync(0xffffffffu, sq, off);
            float o = v / sqrtf(sq + EPS_);
            osh[t] = o;
            if (MODE == 2) out[((size_t)b * NC_ + i) * DC_ + t] = o;
        }
        __syncthreads();

        if (MODE != 2) {
            float wv = 0.f;
#pragma unroll
            for (int k = 0; k < 32; ++k) wv += Wsh[t * 33 + k] * osh[k];
            __half h, l;
            splitf(wv, h, l);
            g_wvh[((size_t)b * NC_ + i) * M_ + t] = h;
            g_wvl[((size_t)b * NC_ + i) * M_ + t] = l;
        }
        __syncthreads();
    }
}

// ---------- fused route: logits + softmax + cx, x staged once ----------
// grid (64 b, 16 seg64), block 256 = 8 warps. Block: 64 j x (32 i logits; 32i x 256m cx).
// smem halves: XH @0 (64*264), XL @16896, CH @33792 (64*40), CL @36352; b1 f32 @38912.
#define RT_XH 0
#define RT_XL 16896
#define RT_CH 33792
#define RT_CL 36352
#define RT_B1 38912
#define RT_SMEM ((38912 + 4224) * 2)     // 86272 B

__global__ void __launch_bounds__(256, 2) k_route() {
    extern __shared__ __half dsm[];
    uint32_t sb = (uint32_t)__cvta_generic_to_shared(dsm);
    int t = threadIdx.x, lane = t & 31, w = t >> 5;
    int g = lane >> 2, tig = lane & 3;
    int b = blockIdx.x, seg = blockIdx.y, j0 = seg * 64;

    // ---- stage X hi/lo [64 j][256 m], pitch 264 ----
#pragma unroll
    for (int c = 0; c < 8; ++c) {
        int lin = t + 256 * c;              // 2048 uint4 per plane
        int j = lin >> 5, mq = lin & 31;
        size_t so = ((size_t)b * J_ + j0 + j) * M_ + mq * 8;
        cpa16(sb + 2u * (RT_XH + j * 264 + mq * 8), g_xh + so);
        cpa16(sb + 2u * (RT_XL + j * 264 + mq * 8), g_xl + so);
    }
    CP_COMMIT; CP_WAIT0;
    __syncthreads();

    // ---- phase 1: logits. warp: jt = w&3 (16 j), ih = w>>2 (16 i = 2 n-tiles) ----
    {
        int jt = w & 3, ih = w >> 2;
        uint32_t aA = sb + 2u * (RT_XH + (jt * 16 + (lane & 15)) * 264) + (lane >> 4) * 16;
        const uint32_t* wvh0 = (const uint32_t*)(g_wvh + ((size_t)b * NC_ + ih * 16 + g) * M_) + tig;
        const uint32_t* wvl0 = (const uint32_t*)(g_wvl + ((size_t)b * NC_ + ih * 16 + g) * M_) + tig;

        float hh[2][4] = {}, lo[2][4] = {};
#pragma unroll
        for (int ks = 0; ks < 16; ++ks) {
            uint32_t ah0, ah1, ah2, ah3, al0, al1, al2, al3;
            ldmx4(ah0, ah1, ah2, ah3, aA + ks * 32);
            ldmx4(al0, al1, al2, al3, aA + 2u * RT_XL + ks * 32);
            uint32_t bh0 = wvh0[ks * 8],        bh1 = wvh0[ks * 8 + 4];
            uint32_t bh2 = wvh0[1024 + ks * 8], bh3 = wvh0[1024 + ks * 8 + 4];
            uint32_t bl0 = wvl0[ks * 8],        bl1 = wvl0[ks * 8 + 4];
            uint32_t bl2 = wvl0[1024 + ks * 8], bl3 = wvl0[1024 + ks * 8 + 4];
            mma16816(hh[0][0], hh[0][1], hh[0][2], hh[0][3], ah0, ah1, ah2, ah3, bh0, bh1);
            mma16816(lo[0][0], lo[0][1], lo[0][2], lo[0][3], al0, al1, al2, al3, bh0, bh1);
            mma16816(lo[0][0], lo[0][1], lo[0][2], lo[0][3], ah0, ah1, ah2, ah3, bl0, bl1);
            mma16816(hh[1][0], hh[1][1], hh[1][2], hh[1][3], ah0, ah1, ah2, ah3, bh2, bh3);
            mma16816(lo[1][0], lo[1][1], lo[1][2], lo[1][3], al0, al1, al2, al3, bh2, bh3);
            mma16816(lo[1][0], lo[1][1], lo[1][2], lo[1][3], ah0, ah1, ah2, ah3, bl2, bl3);
        }

        float* b1 = (float*)(dsm + RT_B1);
#pragma unroll
        for (int nt = 0; nt < 2; ++nt) {
            int row = jt * 16 + g, col = ih * 16 + nt * 8 + 2 * tig;
            b1[row * 33 + col]           = hh[nt][0] + lo[nt][0] * (1.0f / 4096.0f);
            b1[row * 33 + col + 1]       = hh[nt][1] + lo[nt][1] * (1.0f / 4096.0f);
            b1[(row + 8) * 33 + col]     = hh[nt][2] + lo[nt][2] * (1.0f / 4096.0f);
            b1[(row + 8) * 33 + col + 1] = hh[nt][3] + lo[nt][3] * (1.0f / 4096.0f);
        }
    }
    __syncthreads();

    // ---- phase 2: softmax over i per j; c hi/lo -> smem tiles [j][i] pitch 40 ----
    if (t < 64) {
        float* row = (float*)(dsm + RT_B1) + t * 33;
        float mx = row[0];
#pragma unroll
        for (int i = 1; i < 32; ++i) mx = fmaxf(mx, row[i]);
        float s = 0.f;
        float e[32];
#pragma unroll
        for (int i = 0; i < 32; ++i) { e[i] = __expf(row[i] - mx); s += e[i]; }
        float inv = 1.0f / s;
#pragma unroll
        for (int i2 = 0; i2 < 16; ++i2) {
            __half h0, l0, h1, l1;
            splitf(e[2 * i2] * inv, h0, l0);
            splitf(e[2 * i2 + 1] * inv, h1, l1);
            *(__half2*)(dsm + RT_CH + t * 40 + 2 * i2) = __halves2half2(h0, h1);
            *(__half2*)(dsm + RT_CL + t * 40 + 2 * i2) = __halves2half2(l0, l1);
        }
    }
    __syncthreads();

    // ---- phase 3: cx[i][m] = sum_j c[j][i] x[j][m] over this block's 64 j ----
    {
        int mb = w * 32;
        uint32_t cA = sb + 2u * (RT_CH + ((((lane >> 4) & 1) * 8) + (lane & 7)) * 40
                                 + ((lane >> 3) & 1) * 8);
        uint32_t xB = sb + 2u * (RT_XH + ((((lane >> 3) & 1) * 8) + (lane & 7)) * 264
                                 + mb + ((lane >> 4) & 1) * 8);

        float chh[2][4][4] = {}, clo[2][4][4] = {};
#pragma unroll
        for (int ks = 0; ks < 4; ++ks) {          // K = 64 j
            uint32_t a0h0, a0h1, a0h2, a0h3, a1h0, a1h1, a1h2, a1h3;
            uint32_t a0l0, a0l1, a0l2, a0l3, a1l0, a1l1, a1l2, a1l3;
            ldmx4t(a0h0, a0h1, a0h2, a0h3, cA + ks * 1280);
            ldmx4t(a1h0, a1h1, a1h2, a1h3, cA + 32 + ks * 1280);
            ldmx4t(a0l0, a0l1, a0l2, a0l3, cA + 5120 + ks * 1280);
            ldmx4t(a1l0, a1l1, a1l2, a1l3, cA + 5120 + 32 + ks * 1280);

            uint32_t b0h0, b0h1, b0h2, b0h3, b1h0, b1h1, b1h2, b1h3;
            uint32_t b0l0, b0l1, b0l2, b0l3, b1l0, b1l1, b1l2, b1l3;
            ldmx4t(b0h0, b0h1, b0h2, b0h3, xB + ks * 8448);
            ldmx4t(b1h0, b1h1, b1h2, b1h3, xB + 32 + ks * 8448);
            ldmx4t(b0l0, b0l1, b0l2, b0l3, xB + 2u * RT_XL + ks * 8448);
            ldmx4t(b1l0, b1l1, b1l2, b1l3, xB + 2u * RT_XL + 32 + ks * 8448);

#define CX_MMA(it, AH0,AH1,AH2,AH3, AL0,AL1,AL2,AL3) \
            mma16816(chh[it][0][0], chh[it][0][1], chh[it][0][2], chh[it][0][3], AH0,AH1,AH2,AH3, b0h0, b0h1); \
            mma16816(clo[it][0][0], clo[it][0][1], clo[it][0][2], clo[it][0][3], AL0,AL1,AL2,AL3, b0h0, b0h1); \
            mma16816(clo[it][0][0], clo[it][0][1], clo[it][0][2], clo[it][0][3], AH0,AH1,AH2,AH3, b0l0, b0l1); \
            mma16816(chh[it][1][0], chh[it][1][1], chh[it][1][2], chh[it][1][3], AH0,AH1,AH2,AH3, b0h2, b0h3); \
            mma16816(clo[it][1][0], clo[it][1][1], clo[it][1][2], clo[it][1][3], AL0,AL1,AL2,AL3, b0h2, b0h3); \
            mma16816(clo[it][1][0], clo[it][1][1], clo[it][1][2], clo[it][1][3], AH0,AH1,AH2,AH3, b0l2, b0l3); \
            mma16816(chh[it][2][0], chh[it][2][1], chh[it][2][2], chh[it][2][3], AH0,AH1,AH2,AH3, b1h0, b1h1); \
            mma16816(clo[it][2][0], clo[it][2][1], clo[it][2][2], clo[it][2][3], AL0,AL1,AL2,AL3, b1h0, b1h1); \
            mma16816(clo[it][2][0], clo[it][2][1], clo[it][2][2], clo[it][2][3], AH0,AH1,AH2,AH3, b1l0, b1l1); \
            mma16816(chh[it][3][0], chh[it][3][1], chh[it][3][2], chh[it][3][3], AH0,AH1,AH2,AH3, b1h2, b1h3); \
            mma16816(clo[it][3][0], clo[it][3][1], clo[it][3][2], clo[it][3][3], AL0,AL1,AL2,AL3, b1h2, b1h3); \
            mma16816(clo[it][3][0], clo[it][3][1], clo[it][3][2], clo[it][3][3], AH0,AH1,AH2,AH3, b1l2, b1l3);

            CX_MMA(0, a0h0, a0h1, a0h2, a0h3, a0l0, a0l1, a0l2, a0l3)
            CX_MMA(1, a1h0, a1h1, a1h2, a1h3, a1l0, a1l1, a1l2, a1l3)
#undef CX_MMA
        }

#pragma unroll
        for (int it = 0; it < 2; ++it)
#pragma unroll
            for (int nt = 0; nt < 4; ++nt) {
                int i = it * 16 + g;
                int m = mb + nt * 8 + 2 * tig;
                size_t base = (((size_t)seg * B_ + b) * NC_ + i) * M_ + m;
                float2 v0, v1;
                v0.x = chh[it][nt][0] + clo[it][nt][0] * (1.0f / 4096.0f);
                v0.y = chh[it][nt][1] + clo[it][nt][1] * (1.0f / 4096.0f);
                v1.x = chh[it][nt][2] + clo[it][nt][2] * (1.0f / 4096.0f);
                v1.y = chh[it][nt][3] + clo[it][nt][3] * (1.0f / 4096.0f);
                *(float2*)(g_cxp + base)          = v0;
                *(float2*)(g_cxp + base + 8 * M_) = v1;
            }
    }
}

extern "C" void kernel_launch(void* const* d_in, const int* in_sizes, int n_in,
                              void* d_out, int out_size) {
    const float* x = (const float*)d_in[0];
    const float* W = (const float*)d_in[1];
    if (n_in >= 2 && in_sizes[0] < in_sizes[1]) {
        const float* tmp = x; x = W; W = tmp;
    }
    float* out = (float*)d_out;

    cudaFuncSetAttribute(k_route, cudaFuncAttributeMaxDynamicSharedMemorySize, RT_SMEM);

    k_prep<<<dim3(B_, XSEG_), 256>>>(x);
    k_caps<0><<<dim3(NC_, 16), 256>>>(W, out);

    k_route<<<dim3(B_, CSEG_), 256, RT_SMEM>>>();
    k_caps<1><<<dim3(NC_, 16), 256>>>(W, out);

    k_route<<<dim3(B_, CSEG_), 256, RT_SMEM>>>();
    k_caps<2><<<dim3(NC_, 16), 256>>>(W, out);
}